// round 7
// baseline (speedup 1.0000x reference)
#include <cuda_runtime.h>
#include <cstdint>
#include <math.h>

// Fused MoE router: 1-pass tf32 mma.sync GEMM (+ exact double-float fixup of
// low-gap tokens). M=16384 tokens, N=64 experts, K=4096.
// Output f32: [idx 32768][w 32768].

#define NTOK 16384
#define DIMS 4096
#define NEXP 64
#define BM   64
#define KC   32
#define NCH  (DIMS / KC)     // 128
#define LDT  40              // smem row stride (floats); LDS.64 conflict-free
#define GAP_THR 1e-2f
#define CAP  4096

// dynamic smem (bytes)
#define SM_AS   0            // 2 bufs x 64 x 40 f32 = 20480
#define SM_WS   20480        // 20480
#define SM_BIAS 40960        // 64 f32
#define SM_TOT  41216

__device__ int g_cnt = 0;
__device__ int g_susp[CAP];

static __device__ __forceinline__ uint32_t tf32r(float x) {
    uint32_t u;
    asm("cvt.rna.tf32.f32 %0, %1;" : "=r"(u) : "f"(x));
    return u;
}

static __device__ __forceinline__ void mma8(float c[4],
                                            uint32_t a0, uint32_t a1, uint32_t a2, uint32_t a3,
                                            uint32_t b0, uint32_t b1) {
    asm volatile(
        "mma.sync.aligned.m16n8k8.row.col.f32.tf32.tf32.f32 "
        "{%0,%1,%2,%3}, {%4,%5,%6,%7}, {%8,%9}, {%0,%1,%2,%3};"
        : "+f"(c[0]), "+f"(c[1]), "+f"(c[2]), "+f"(c[3])
        : "r"(a0), "r"(a1), "r"(a2), "r"(a3), "r"(b0), "r"(b1));
}

// ---------------- kernel 1: main GEMM + epilogue ----------------
// Smem tile layout per 8-col group: columns stored interleaved [0,4,1,5,2,6,3,7]
// so a fragment thread reads its (k, k+4) pair as one LDS.64.
__global__ __launch_bounds__(256, 2)
void k_main(const float* __restrict__ x,
            const float* __restrict__ W,
            const float* __restrict__ bias,
            float* __restrict__ out)
{
    extern __shared__ __align__(16) char smem[];
    float* As    = (float*)(smem + SM_AS);     // [2][64][LDT]
    float* Ws    = (float*)(smem + SM_WS);     // [2][64][LDT]
    float* biasS = (float*)(smem + SM_BIAS);

    const int tid  = threadIdx.x;
    const int wid  = tid >> 5;
    const int lane = tid & 31;
    const int wm   = wid & 1;          // M half: wm*32, two m16 tiles
    const int wn   = wid >> 1;         // N quarter: wn*16, two n8 tiles
    const int bm   = blockIdx.x * BM;

    if (tid < NEXP) biasS[tid] = bias[tid];

    // staging slots: u=0,1 -> A tile (64x32), u=2,3 -> W tile (64x32).
    // Each slot: 2 LDG.64 (cols c..c+1 and c+4..c+5) -> 1 interleaved STS.128.
    const float* gp[4];
    int soff[4];
#pragma unroll
    for (int u = 0; u < 4; u++) {
        int f = tid + 256 * (u & 1);
        int row = f >> 3, rem = f & 7, g = rem >> 1, s = rem & 1;
        const float* basep = (u < 2) ? (x + (size_t)(bm + row) * DIMS)
                                     : (W + (size_t)row * DIMS);
        gp[u]   = basep + g * 8 + 2 * s;
        soff[u] = row * LDT + g * 8 + s * 4;
    }

    int aoff[2], boff[2];
#pragma unroll
    for (int mt = 0; mt < 2; mt++)
        aoff[mt] = (wm * 32 + mt * 16 + (lane >> 2)) * LDT + (lane & 3) * 2;
#pragma unroll
    for (int nt = 0; nt < 2; nt++)
        boff[nt] = (wn * 16 + nt * 8 + (lane >> 2)) * LDT + (lane & 3) * 2;

    float acc[2][2][4];
#pragma unroll
    for (int mt = 0; mt < 2; mt++)
#pragma unroll
        for (int nt = 0; nt < 2; nt++)
#pragma unroll
            for (int q = 0; q < 4; q++) acc[mt][nt][q] = 0.0f;

    // 2-deep register prefetch: set s2 holds chunk with (chunk & 1) == s2
    float2 lo[2][4], hi[2][4];
#pragma unroll
    for (int s2 = 0; s2 < 2; s2++)
#pragma unroll
        for (int u = 0; u < 4; u++) {
            lo[s2][u] = *(const float2*)(gp[u] + s2 * KC);
            hi[s2][u] = *(const float2*)(gp[u] + s2 * KC + 4);
        }

    for (int i = 0; i < NCH; i++) {
        const int b = i & 1;
        float* Ad = As + b * 64 * LDT;
        float* Wd = Ws + b * 64 * LDT;

        // store set b (tf32-converted, interleaved pairs), conflict-free STS.128
#pragma unroll
        for (int u = 0; u < 4; u++) {
            float4 v;
            v.x = __uint_as_float(tf32r(lo[b][u].x));
            v.y = __uint_as_float(tf32r(hi[b][u].x));
            v.z = __uint_as_float(tf32r(lo[b][u].y));
            v.w = __uint_as_float(tf32r(hi[b][u].y));
            *(float4*)(((u < 2) ? Ad : Wd) + soff[u]) = v;
        }

        // refill set b with chunk i+2 (~2 iterations of latency cover)
        if (i + 2 < NCH) {
            const int ko = (i + 2) * KC;
#pragma unroll
            for (int u = 0; u < 4; u++) {
                lo[b][u] = *(const float2*)(gp[u] + ko);
                hi[b][u] = *(const float2*)(gp[u] + ko + 4);
            }
        }
        __syncthreads();

        // compute buf b: 4 k-steps, LDS.64 fragments
        const uint32_t* Au = (const uint32_t*)Ad;
        const uint32_t* Wu = (const uint32_t*)Wd;
#pragma unroll
        for (int ks = 0; ks < 4; ks++) {
            uint2 pa0[2], pa1[2], pb[2];
#pragma unroll
            for (int mt = 0; mt < 2; mt++) {
                pa0[mt] = *(const uint2*)(Au + aoff[mt] + ks * 8);
                pa1[mt] = *(const uint2*)(Au + aoff[mt] + 8 * LDT + ks * 8);
            }
#pragma unroll
            for (int nt = 0; nt < 2; nt++)
                pb[nt] = *(const uint2*)(Wu + boff[nt] + ks * 8);
#pragma unroll
            for (int mt = 0; mt < 2; mt++)
#pragma unroll
                for (int nt = 0; nt < 2; nt++)
                    mma8(acc[mt][nt], pa0[mt].x, pa1[mt].x, pa0[mt].y, pa1[mt].y,
                         pb[nt].x, pb[nt].y);
        }
    }
    __syncthreads();   // all computes done; smem free for logits

    // epilogue: logits -> smem [64][66]
    float* lg = (float*)(smem + SM_AS);
    {
#pragma unroll
        for (int mt = 0; mt < 2; mt++)
#pragma unroll
            for (int nt = 0; nt < 2; nt++) {
                int r = wm * 32 + mt * 16 + (lane >> 2);
                int c = wn * 16 + nt * 8 + (lane & 3) * 2;
                *(float2*)(lg + r * 66 + c)       = make_float2(acc[mt][nt][0], acc[mt][nt][1]);
                *(float2*)(lg + (r + 8) * 66 + c) = make_float2(acc[mt][nt][2], acc[mt][nt][3]);
            }
    }
    __syncthreads();

    if (tid < BM) {
        const float* row = lg + tid * 66;
        float m1 = -INFINITY, m2 = -INFINITY, m3 = -INFINITY;
        int   i1 = 0, i2 = 0;
#pragma unroll
        for (int e = 0; e < NEXP; e++) {
            float v = row[e] + biasS[e];
            if (v > m1)      { m3 = m2; m2 = m1; i2 = i1; m1 = v; i1 = e; }
            else if (v > m2) { m3 = m2; m2 = v;  i2 = e; }
            else if (v > m3) { m3 = v; }
        }
        const int gt = bm + tid;
        if ((m1 - m2 < GAP_THR) || (m2 - m3 < GAP_THR)) {
            int slot = atomicAdd(&g_cnt, 1);
            if (slot < CAP) g_susp[slot] = gt;
        }
        float e21 = expf(m2 - m1);
        float w1v = 1.0f / (1.0f + e21);
        out[2 * gt + 0] = (float)i1;
        out[2 * gt + 1] = (float)i2;
        out[2 * NTOK + 2 * gt + 0] = w1v;
        out[2 * NTOK + 2 * gt + 1] = e21 * w1v;
    }
}

// ---------------- kernel 2: fused exact fixup (logits + top-2 + softmax) ----------------
static __device__ __forceinline__ void two_sum(float a, float b, float& s, float& e) {
    s = a + b;
    float v = s - a;
    e = (a - (s - v)) + (b - v);
}

__global__ __launch_bounds__(256)
void k_fix(const float* __restrict__ x,
           const float* __restrict__ W,
           const float* __restrict__ bias,
           float* __restrict__ out)
{
    __shared__ float  xs[DIMS];
    __shared__ double lgd[NEXP];
    const int tid  = threadIdx.x;
    const int w    = tid >> 5;
    const int lane = tid & 31;
    const int cnt  = min(g_cnt, CAP);

    for (int s = blockIdx.x; s < cnt; s += gridDim.x) {
        const int t = g_susp[s];

        const float4* xr = (const float4*)(x + (size_t)t * DIMS);
        for (int i = tid; i < DIMS / 4; i += 256) ((float4*)xs)[i] = xr[i];
        __syncthreads();

        // warp w computes experts w*8 .. w*8+7 with compensated fp32 dot
#pragma unroll 1
        for (int r = 0; r < 8; r++) {
            const int e = w * 8 + r;
            const float4* wr = (const float4*)(W + (size_t)e * DIMS);
            float hi = 0.0f, c = 0.0f;
#pragma unroll 4
            for (int it = 0; it < 32; it++) {
                float4 xv = ((const float4*)xs)[lane + 32 * it];
                float4 wv = wr[lane + 32 * it];
                float pr, pe, se;
                pr = xv.x * wv.x; pe = fmaf(xv.x, wv.x, -pr); two_sum(hi, pr, hi, se); c += se + pe;
                pr = xv.y * wv.y; pe = fmaf(xv.y, wv.y, -pr); two_sum(hi, pr, hi, se); c += se + pe;
                pr = xv.z * wv.z; pe = fmaf(xv.z, wv.z, -pr); two_sum(hi, pr, hi, se); c += se + pe;
                pr = xv.w * wv.w; pe = fmaf(xv.w, wv.w, -pr); two_sum(hi, pr, hi, se); c += se + pe;
            }
#pragma unroll
            for (int off = 16; off > 0; off >>= 1) {
                float oh = __shfl_down_sync(0xffffffffu, hi, off);
                float oc = __shfl_down_sync(0xffffffffu, c,  off);
                float ns, ne;
                two_sum(hi, oh, ns, ne);
                hi = ns; c = c + oc + ne;
            }
            if (lane == 0) lgd[e] = (double)hi + (double)c + (double)bias[e];
        }
        __syncthreads();

        if (tid == 0) {
            double m1 = -1e300, m2 = -1e300;
            int i1 = 0, i2 = 0;
            for (int e = 0; e < NEXP; e++) {
                double v = lgd[e];
                if (v > m1)      { m2 = m1; i2 = i1; m1 = v; i1 = e; }
                else if (v > m2) { m2 = v;  i2 = e; }
            }
            double e21 = exp(m2 - m1);
            double w1v = 1.0 / (1.0 + e21);
            out[2 * t + 0] = (float)i1;
            out[2 * t + 1] = (float)i2;
            out[2 * NTOK + 2 * t + 0] = (float)w1v;
            out[2 * NTOK + 2 * t + 1] = (float)(e21 * w1v);
        }
        __syncthreads();
    }
}

// ---------------- kernel 3: reset suspect counter for next call ----------------
__global__ void k_zero() { if (threadIdx.x == 0) g_cnt = 0; }

extern "C" void kernel_launch(void* const* d_in, const int* in_sizes, int n_in,
                              void* d_out, int out_size)
{
    const float* x = (const float*)d_in[0];   // (4, 4096, 4096) f32
    const float* W = (const float*)d_in[1];   // (64, 4096) f32
    const float* b = (const float*)d_in[2];   // (64,) f32
    float* out = (float*)d_out;
    (void)in_sizes; (void)n_in; (void)out_size;

    cudaFuncSetAttribute(k_main, cudaFuncAttributeMaxDynamicSharedMemorySize, SM_TOT);

    k_main<<<NTOK / BM, 256, SM_TOT>>>(x, W, b, out);   // 256 CTAs
    k_fix<<<1024, 256>>>(x, W, b, out);
    k_zero<<<1, 32>>>();
}

// round 11
// speedup vs baseline: 1.4915x; 1.4915x over previous
#include <cuda_runtime.h>
#include <cstdint>
#include <math.h>

// MoE router: logits = x @ W^T + b, top-2, masked softmax.
// k_prep: W -> tf32(rna) once. k_main: 2-pass exact-split tf32 mma.sync
// (xh = trunc13(x) exactly representable, xl = x-xh; W pre-rounded) ->
// logit err sigma ~1.4e-4; suspects (gap < 1.5e-3) fixed exactly in k_fix.
// Output f32: [idx 32768][w 32768].

#define NTOK 16384
#define DIMS 4096
#define NEXP 64
#define TN   64              // tokens per CTA
#define KC   32
#define NCH  (DIMS / KC)     // 128
#define LDT  36              // smem tile row stride (floats): 128B data + 16B pad
#define NST  3               // cp.async stages
#define GAP_THR 1.5e-3f
#define CAP  8192

#define TILE_B   (64 * LDT * 4)          // 9216 B (one 64x32 f32 tile)
#define STAGE_B  (2 * TILE_B)            // W tile + x tile
#define SM_BIAS  (NST * STAGE_B)         // 55296
#define SM_TOT   (SM_BIAS + 256)

__device__ int   g_cnt = 0;
__device__ int   g_susp[CAP];
__device__ float g_Wt[NEXP * DIMS];      // tf32(rna)-rounded W

static __device__ __forceinline__ uint32_t smem_u32(const void* p) {
    uint32_t a;
    asm("{ .reg .u64 t; cvta.to.shared.u64 t, %1; cvt.u32.u64 %0, t; }" : "=r"(a) : "l"(p));
    return a;
}
static __device__ __forceinline__ void cp16(uint32_t dst, const void* src) {
    asm volatile("cp.async.cg.shared.global [%0], [%1], 16;" :: "r"(dst), "l"(src) : "memory");
}
#define CP_COMMIT() asm volatile("cp.async.commit_group;" ::: "memory")
#define CP_WAIT1()  asm volatile("cp.async.wait_group 1;" ::: "memory")
#define CP_WAIT0()  asm volatile("cp.async.wait_group 0;" ::: "memory")

static __device__ __forceinline__ void mma8(float c[4],
                                            uint32_t a0, uint32_t a1, uint32_t a2, uint32_t a3,
                                            uint32_t b0, uint32_t b1) {
    asm volatile(
        "mma.sync.aligned.m16n8k8.row.col.f32.tf32.tf32.f32 "
        "{%0,%1,%2,%3}, {%4,%5,%6,%7}, {%8,%9}, {%0,%1,%2,%3};"
        : "+f"(c[0]), "+f"(c[1]), "+f"(c[2]), "+f"(c[3])
        : "r"(a0), "r"(a1), "r"(a2), "r"(a3), "r"(b0), "r"(b1));
}

// ---------------- kernel 0: round W to tf32 (rna) once ----------------
__global__ __launch_bounds__(256)
void k_prep(const float* __restrict__ W)
{
    int base = (blockIdx.x * 256 + threadIdx.x) * 4;
    const int total = NEXP * DIMS;
    for (int i = base; i < total; i += gridDim.x * 256 * 4) {
        float4 v = *(const float4*)(W + i);
        uint4 u;
        asm("cvt.rna.tf32.f32 %0, %1;" : "=r"(u.x) : "f"(v.x));
        asm("cvt.rna.tf32.f32 %0, %1;" : "=r"(u.y) : "f"(v.y));
        asm("cvt.rna.tf32.f32 %0, %1;" : "=r"(u.z) : "f"(v.z));
        asm("cvt.rna.tf32.f32 %0, %1;" : "=r"(u.w) : "f"(v.w));
        *(uint4*)(g_Wt + i) = u;
    }
}

// ---------------- kernel 1: main GEMM + epilogue ----------------
// A operand = W (4 m16 tiles), B operand = tokens (8 n8 tiles per CTA).
// 8 warps = 2 mt-groups x 4 nt-groups; warp covers 2 m16 x 2 n8.
__global__ __launch_bounds__(256, 2)
void k_main(const float* __restrict__ x,
            const float* __restrict__ bias,
            float* __restrict__ out)
{
    extern __shared__ __align__(16) char smem[];
    const uint32_t sb = smem_u32(smem);
    float* biasS = (float*)(smem + SM_BIAS);

    const int tid  = threadIdx.x;
    const int wid  = tid >> 5;
    const int lane = tid & 31;
    const int wm   = wid & 1;          // expert half (2 m16 tiles each)
    const int wn   = wid >> 1;         // token quarter (2 n8 tiles each)
    const int bm   = blockIdx.x * TN;  // token base

    if (tid < NEXP) biasS[tid] = bias[tid];

    // cp.async staging: each tile is 512 x 16B chunks; thread does chunks tid, tid+256.
    // chunk c -> row c>>3, quad c&7 ; src row-major stride DIMS; dst row stride LDT.
    const float* wsrc[2]; const float* xsrc[2]; uint32_t wdst[2], xdst[2];
#pragma unroll
    for (int j = 0; j < 2; j++) {
        int c = tid + 256 * j, row = c >> 3, q = c & 7;
        wsrc[j] = g_Wt + (size_t)row * DIMS + q * 4;
        xsrc[j] = x + (size_t)(bm + row) * DIMS + q * 4;
        wdst[j] = sb + row * (LDT * 4) + q * 16;
        xdst[j] = sb + TILE_B + row * (LDT * 4) + q * 16;
    }

    // fragment offsets (float index within a stage)
    int aoff[2], boff[2];
#pragma unroll
    for (int mt = 0; mt < 2; mt++)
        aoff[mt] = (wm * 32 + mt * 16 + (lane >> 2)) * LDT + (lane & 3);
#pragma unroll
    for (int nt = 0; nt < 2; nt++)
        boff[nt] = (wn * 16 + nt * 8 + (lane >> 2)) * LDT + (lane & 3);

    float acc[2][2][4];
#pragma unroll
    for (int mt = 0; mt < 2; mt++)
#pragma unroll
        for (int nt = 0; nt < 2; nt++)
#pragma unroll
            for (int q = 0; q < 4; q++) acc[mt][nt][q] = 0.0f;

    // prologue: stages for chunks 0,1
#pragma unroll
    for (int p = 0; p < 2; p++) {
        uint32_t so = p * STAGE_B;
#pragma unroll
        for (int j = 0; j < 2; j++) {
            cp16(wdst[j] + so, wsrc[j] + p * KC);
            cp16(xdst[j] + so, xsrc[j] + p * KC);
        }
        CP_COMMIT();
    }

    for (int i = 0; i < NCH; i++) {
        const int slot = i % NST;
        CP_WAIT1();
        __syncthreads();

        // issue chunk i+2 into slot (i+2)%NST (freed by last iteration's compute)
        if (i + 2 < NCH) {
            uint32_t so = ((i + 2) % NST) * STAGE_B;
            const int ko = (i + 2) * KC;
#pragma unroll
            for (int j = 0; j < 2; j++) {
                cp16(wdst[j] + so, wsrc[j] + ko);
                cp16(xdst[j] + so, xsrc[j] + ko);
            }
        }
        CP_COMMIT();

        // compute slot: 4 k-steps, 2 passes (xh implicit-trunc, xl exact tail)
        const uint32_t* Wt = (const uint32_t*)(smem + slot * STAGE_B);
        const uint32_t* Xt = (const uint32_t*)(smem + slot * STAGE_B + TILE_B);
#pragma unroll
        for (int ks = 0; ks < 4; ks++) {
            const int k8 = ks * 8;
            uint32_t a[2][4];
#pragma unroll
            for (int mt = 0; mt < 2; mt++) {
                a[mt][0] = Wt[aoff[mt] + k8];
                a[mt][1] = Wt[aoff[mt] + 8 * LDT + k8];
                a[mt][2] = Wt[aoff[mt] + k8 + 4];
                a[mt][3] = Wt[aoff[mt] + 8 * LDT + k8 + 4];
            }
            uint32_t bh[2][2], bl[2][2];
#pragma unroll
            for (int nt = 0; nt < 2; nt++) {
                uint32_t r0 = Xt[boff[nt] + k8];
                uint32_t r1 = Xt[boff[nt] + k8 + 4];
                bh[nt][0] = r0 & 0xFFFFE000u;
                bh[nt][1] = r1 & 0xFFFFE000u;
                bl[nt][0] = __float_as_uint(__uint_as_float(r0) - __uint_as_float(bh[nt][0]));
                bl[nt][1] = __float_as_uint(__uint_as_float(r1) - __uint_as_float(bh[nt][1]));
            }
#pragma unroll
            for (int mt = 0; mt < 2; mt++)
#pragma unroll
                for (int nt = 0; nt < 2; nt++) {
                    mma8(acc[mt][nt], a[mt][0], a[mt][1], a[mt][2], a[mt][3], bh[nt][0], bh[nt][1]);
                    mma8(acc[mt][nt], a[mt][0], a[mt][1], a[mt][2], a[mt][3], bl[nt][0], bl[nt][1]);
                }
        }
    }
    CP_WAIT0();
    __syncthreads();

    // epilogue: scatter acc -> lg[token][expert] (stride 68), conflict-free STS.32
    float* lg = (float*)smem;
    {
#pragma unroll
        for (int mt = 0; mt < 2; mt++) {
            const int m = wm * 32 + mt * 16 + (lane >> 2);
#pragma unroll
            for (int nt = 0; nt < 2; nt++) {
                const int n = wn * 16 + nt * 8 + (lane & 3) * 2;
                lg[n * 68 + m]           = acc[mt][nt][0];
                lg[(n + 1) * 68 + m]     = acc[mt][nt][1];
                lg[n * 68 + m + 8]       = acc[mt][nt][2];
                lg[(n + 1) * 68 + m + 8] = acc[mt][nt][3];
            }
        }
    }
    __syncthreads();

    if (tid < TN) {
        const float* row = lg + tid * 68;
        float m1 = -INFINITY, m2 = -INFINITY, m3 = -INFINITY;
        int   i1 = 0, i2 = 0;
#pragma unroll
        for (int e = 0; e < NEXP; e++) {
            float v = row[e] + biasS[e];
            if (v > m1)      { m3 = m2; m2 = m1; i2 = i1; m1 = v; i1 = e; }
            else if (v > m2) { m3 = m2; m2 = v;  i2 = e; }
            else if (v > m3) { m3 = v; }
        }
        const int gt = bm + tid;
        if ((m1 - m2 < GAP_THR) || (m2 - m3 < GAP_THR)) {
            int slot = atomicAdd(&g_cnt, 1);
            if (slot < CAP) g_susp[slot] = gt;
        }
        float e21 = expf(m2 - m1);
        float w1v = 1.0f / (1.0f + e21);
        out[2 * gt + 0] = (float)i1;
        out[2 * gt + 1] = (float)i2;
        out[2 * NTOK + 2 * gt + 0] = w1v;
        out[2 * NTOK + 2 * gt + 1] = e21 * w1v;
    }
}

// ---------------- kernel 2: exact fixup, 4 suspects per block ----------------
#define FIX_SM (4 * DIMS * 4 + 4 * NEXP * 8)    // 4 x-tiles + lgd[4][64] doubles

__global__ __launch_bounds__(256)
void k_fix(const float* __restrict__ x,
           const float* __restrict__ W,
           const float* __restrict__ bias,
           float* __restrict__ out)
{
    extern __shared__ __align__(16) char fsm[];
    float*  xs  = (float*)fsm;                    // [4][DIMS]
    double* lgd = (double*)(fsm + 4 * DIMS * 4);  // [4][NEXP]

    const int tid  = threadIdx.x;
    const int w    = tid >> 5;
    const int lane = tid & 31;
    const int cnt  = min(g_cnt, CAP);

    for (int s0 = blockIdx.x * 4; s0 < cnt; s0 += gridDim.x * 4) {
        const int ngrp = min(4, cnt - s0);

        for (int g = 0; g < ngrp; g++) {
            const float4* xr = (const float4*)(x + (size_t)g_susp[s0 + g] * DIMS);
            for (int i = tid; i < DIMS / 4; i += 256)
                ((float4*)(xs + g * DIMS))[i] = xr[i];
        }
        __syncthreads();

        // warp w: experts w*8 .. w*8+7; 4 independent fp32 FMA chains per token
#pragma unroll 1
        for (int r = 0; r < 8; r++) {
            const int e = w * 8 + r;
            const float4* wr = (const float4*)(W + (size_t)e * DIMS);
            float4 s[4];
#pragma unroll
            for (int g = 0; g < 4; g++) s[g] = make_float4(0.f, 0.f, 0.f, 0.f);
#pragma unroll 4
            for (int it = 0; it < 32; it++) {
                float4 wv = wr[lane + 32 * it];
#pragma unroll
                for (int g = 0; g < 4; g++) {
                    float4 xv = ((const float4*)(xs + g * DIMS))[lane + 32 * it];
                    s[g].x = fmaf(xv.x, wv.x, s[g].x);
                    s[g].y = fmaf(xv.y, wv.y, s[g].y);
                    s[g].z = fmaf(xv.z, wv.z, s[g].z);
                    s[g].w = fmaf(xv.w, wv.w, s[g].w);
                }
            }
#pragma unroll
            for (int g = 0; g < 4; g++) {
                double d = ((double)s[g].x + (double)s[g].y) + ((double)s[g].z + (double)s[g].w);
#pragma unroll
                for (int off = 16; off > 0; off >>= 1)
                    d += __shfl_down_sync(0xffffffffu, d, off);
                if (lane == 0) lgd[g * NEXP + e] = d + (double)bias[e];
            }
        }
        __syncthreads();

        if (tid < ngrp) {
            const int t = g_susp[s0 + tid];
            const double* row = lgd + tid * NEXP;
            double m1 = -1e300, m2 = -1e300;
            int i1 = 0, i2 = 0;
            for (int e = 0; e < NEXP; e++) {
                double v = row[e];
                if (v > m1)      { m2 = m1; i2 = i1; m1 = v; i1 = e; }
                else if (v > m2) { m2 = v;  i2 = e; }
            }
            double e21 = exp(m2 - m1);
            double w1v = 1.0 / (1.0 + e21);
            out[2 * t + 0] = (float)i1;
            out[2 * t + 1] = (float)i2;
            out[2 * NTOK + 2 * t + 0] = (float)w1v;
            out[2 * NTOK + 2 * t + 1] = (float)(e21 * w1v);
        }
        __syncthreads();
    }
}

// ---------------- kernel 3: reset suspect counter ----------------
__global__ void k_zero() { if (threadIdx.x == 0) g_cnt = 0; }

extern "C" void kernel_launch(void* const* d_in, const int* in_sizes, int n_in,
                              void* d_out, int out_size)
{
    const float* x = (const float*)d_in[0];   // (4, 4096, 4096) f32
    const float* W = (const float*)d_in[1];   // (64, 4096) f32
    const float* b = (const float*)d_in[2];   // (64,) f32
    float* out = (float*)d_out;
    (void)in_sizes; (void)n_in; (void)out_size;

    cudaFuncSetAttribute(k_main, cudaFuncAttributeMaxDynamicSharedMemorySize, SM_TOT);
    cudaFuncSetAttribute(k_fix,  cudaFuncAttributeMaxDynamicSharedMemorySize, FIX_SM);

    k_prep<<<64, 256>>>(W);
    k_main<<<NTOK / TN, 256, SM_TOT>>>(x, b, out);
    k_fix<<<256, 256, FIX_SM>>>(x, W, b, out);
    k_zero<<<1, 32>>>();
}

// round 12
// speedup vs baseline: 1.9557x; 1.3112x over previous
#include <cuda_runtime.h>
#include <cstdint>
#include <math.h>

// MoE router: logits = x @ W^T + b, top-2, masked softmax.
// k_prep: W -> tf32(rna) once (+ resets suspect counter).
// k_main: single-pass tf32 mma.sync (x rounded rna at fragment load) ->
//         gap error sigma ~3.5e-4; tokens with top-2/3 gap < 8e-3 flagged.
// k_fix:  exact recompute (fp32 chains + double reduce) of flagged tokens.
// Output f32: [idx 32768][w 32768].

#define NTOK 16384
#define DIMS 4096
#define NEXP 64
#define TN   64              // tokens per CTA
#define KC   32
#define NCH  (DIMS / KC)     // 128
#define LDT  36              // smem tile row stride (floats)
#define NST  4               // cp.async ring slots
#define GAP_THR 8e-3f
#define CAP  16384

#define TILE_B   (64 * LDT * 4)          // 9216 B
#define STAGE_B  (2 * TILE_B)            // W tile + x tile
#define SM_BIAS  (NST * STAGE_B)         // 73728
#define SM_TOT   (SM_BIAS + 256)

__device__ int   g_cnt = 0;
__device__ int   g_susp[CAP];
__device__ float g_Wt[NEXP * DIMS];      // tf32(rna)-rounded W

static __device__ __forceinline__ uint32_t smem_u32(const void* p) {
    uint32_t a;
    asm("{ .reg .u64 t; cvta.to.shared.u64 t, %1; cvt.u32.u64 %0, t; }" : "=r"(a) : "l"(p));
    return a;
}
static __device__ __forceinline__ void cp16(uint32_t dst, const void* src) {
    asm volatile("cp.async.cg.shared.global [%0], [%1], 16;" :: "r"(dst), "l"(src) : "memory");
}
#define CP_COMMIT() asm volatile("cp.async.commit_group;" ::: "memory")
#define CP_WAIT2()  asm volatile("cp.async.wait_group 2;" ::: "memory")

static __device__ __forceinline__ uint32_t tf32r(float x) {
    uint32_t u;
    asm("cvt.rna.tf32.f32 %0, %1;" : "=r"(u) : "f"(x));
    return u;
}

static __device__ __forceinline__ void mma8(float c[4],
                                            uint32_t a0, uint32_t a1, uint32_t a2, uint32_t a3,
                                            uint32_t b0, uint32_t b1) {
    asm volatile(
        "mma.sync.aligned.m16n8k8.row.col.f32.tf32.tf32.f32 "
        "{%0,%1,%2,%3}, {%4,%5,%6,%7}, {%8,%9}, {%0,%1,%2,%3};"
        : "+f"(c[0]), "+f"(c[1]), "+f"(c[2]), "+f"(c[3])
        : "r"(a0), "r"(a1), "r"(a2), "r"(a3), "r"(b0), "r"(b1));
}

// ---------------- kernel 0: round W to tf32 (rna); reset counter ----------------
__global__ __launch_bounds__(256)
void k_prep(const float* __restrict__ W)
{
    if (blockIdx.x == 0 && threadIdx.x == 0) g_cnt = 0;
    int base = (blockIdx.x * 256 + threadIdx.x) * 4;
    const int total = NEXP * DIMS;
    for (int i = base; i < total; i += gridDim.x * 256 * 4) {
        float4 v = *(const float4*)(W + i);
        uint4 u;
        u.x = tf32r(v.x); u.y = tf32r(v.y); u.z = tf32r(v.z); u.w = tf32r(v.w);
        *(uint4*)(g_Wt + i) = u;
    }
}

// ---------------- kernel 1: main GEMM + epilogue ----------------
// A = W (4 m16 tiles), B = tokens (8 n8 tiles/CTA). Warp: 2 m16 x 2 n8.
__global__ __launch_bounds__(256, 2)
void k_main(const float* __restrict__ x,
            const float* __restrict__ bias,
            float* __restrict__ out)
{
    extern __shared__ __align__(16) char smem[];
    const uint32_t sb = smem_u32(smem);
    float* biasS = (float*)(smem + SM_BIAS);

    const int tid  = threadIdx.x;
    const int wid  = tid >> 5;
    const int lane = tid & 31;
    const int wm   = wid & 1;
    const int wn   = wid >> 1;
    const int bm   = blockIdx.x * TN;

    if (tid < NEXP) biasS[tid] = bias[tid];

    const float* wsrc[2]; const float* xsrc[2]; uint32_t wdst[2], xdst[2];
#pragma unroll
    for (int j = 0; j < 2; j++) {
        int c = tid + 256 * j, row = c >> 3, q = c & 7;
        wsrc[j] = g_Wt + (size_t)row * DIMS + q * 4;
        xsrc[j] = x + (size_t)(bm + row) * DIMS + q * 4;
        wdst[j] = sb + row * (LDT * 4) + q * 16;
        xdst[j] = sb + TILE_B + row * (LDT * 4) + q * 16;
    }

    int aoff[2], boff[2];
#pragma unroll
    for (int mt = 0; mt < 2; mt++)
        aoff[mt] = (wm * 32 + mt * 16 + (lane >> 2)) * LDT + (lane & 3);
#pragma unroll
    for (int nt = 0; nt < 2; nt++)
        boff[nt] = (wn * 16 + nt * 8 + (lane >> 2)) * LDT + (lane & 3);

    float acc[2][2][4];
#pragma unroll
    for (int mt = 0; mt < 2; mt++)
#pragma unroll
        for (int nt = 0; nt < 2; nt++)
#pragma unroll
            for (int q = 0; q < 4; q++) acc[mt][nt][q] = 0.0f;

    // prologue: chunks 0,1 into slots 0,1
#pragma unroll
    for (int p = 0; p < 2; p++) {
        uint32_t so = p * STAGE_B;
#pragma unroll
        for (int j = 0; j < 2; j++) {
            cp16(wdst[j] + so, wsrc[j] + p * KC);
            cp16(xdst[j] + so, xsrc[j] + p * KC);
        }
        CP_COMMIT();
    }

    for (int i = 0; i < NCH; i++) {
        // issue chunk i+2 into slot (i+2)%4 (held chunk i-2: all warps past it
        // due to iter i-1's barrier), THEN wait with 2 groups still in flight.
        if (i + 2 < NCH) {
            uint32_t so = ((i + 2) % NST) * STAGE_B;
            const int ko = (i + 2) * KC;
#pragma unroll
            for (int j = 0; j < 2; j++) {
                cp16(wdst[j] + so, wsrc[j] + ko);
                cp16(xdst[j] + so, xsrc[j] + ko);
            }
        }
        CP_COMMIT();
        CP_WAIT2();            // chunk i's group complete; i+1, i+2 may pend
        __syncthreads();

        const uint32_t* Wt = (const uint32_t*)(smem + (i % NST) * STAGE_B);
        const uint32_t* Xt = (const uint32_t*)(smem + (i % NST) * STAGE_B + TILE_B);
#pragma unroll
        for (int ks = 0; ks < 4; ks++) {
            const int k8 = ks * 8;
            uint32_t a[2][4];
#pragma unroll
            for (int mt = 0; mt < 2; mt++) {
                a[mt][0] = Wt[aoff[mt] + k8];
                a[mt][1] = Wt[aoff[mt] + 8 * LDT + k8];
                a[mt][2] = Wt[aoff[mt] + k8 + 4];
                a[mt][3] = Wt[aoff[mt] + 8 * LDT + k8 + 4];
            }
            uint32_t b0[2], b1[2];
#pragma unroll
            for (int nt = 0; nt < 2; nt++) {
                b0[nt] = tf32r(__uint_as_float(Xt[boff[nt] + k8]));
                b1[nt] = tf32r(__uint_as_float(Xt[boff[nt] + k8 + 4]));
            }
#pragma unroll
            for (int mt = 0; mt < 2; mt++)
#pragma unroll
                for (int nt = 0; nt < 2; nt++)
                    mma8(acc[mt][nt], a[mt][0], a[mt][1], a[mt][2], a[mt][3],
                         b0[nt], b1[nt]);
        }
        __syncthreads();       // compute done before next iter's cp overwrites
    }

    // epilogue: scatter acc -> lg[token][expert] (stride 68)
    float* lg = (float*)smem;
#pragma unroll
    for (int mt = 0; mt < 2; mt++) {
        const int m = wm * 32 + mt * 16 + (lane >> 2);
#pragma unroll
        for (int nt = 0; nt < 2; nt++) {
            const int n = wn * 16 + nt * 8 + (lane & 3) * 2;
            lg[n * 68 + m]           = acc[mt][nt][0];
            lg[(n + 1) * 68 + m]     = acc[mt][nt][1];
            lg[n * 68 + m + 8]       = acc[mt][nt][2];
            lg[(n + 1) * 68 + m + 8] = acc[mt][nt][3];
        }
    }
    __syncthreads();

    if (tid < TN) {
        const float* row = lg + tid * 68;
        float m1 = -INFINITY, m2 = -INFINITY, m3 = -INFINITY;
        int   i1 = 0, i2 = 0;
#pragma unroll
        for (int e = 0; e < NEXP; e++) {
            float v = row[e] + biasS[e];
            if (v > m1)      { m3 = m2; m2 = m1; i2 = i1; m1 = v; i1 = e; }
            else if (v > m2) { m3 = m2; m2 = v;  i2 = e; }
            else if (v > m3) { m3 = v; }
        }
        const int gt = bm + tid;
        if ((m1 - m2 < GAP_THR) || (m2 - m3 < GAP_THR)) {
            int slot = atomicAdd(&g_cnt, 1);
            if (slot < CAP) g_susp[slot] = gt;
        }
        float e21 = expf(m2 - m1);
        float w1v = 1.0f / (1.0f + e21);
        out[2 * gt + 0] = (float)i1;
        out[2 * gt + 1] = (float)i2;
        out[2 * NTOK + 2 * gt + 0] = w1v;
        out[2 * NTOK + 2 * gt + 1] = e21 * w1v;
    }
}

// ---------------- kernel 2: exact fixup, 8 suspects per block ----------------
#define FIX_SM (8 * DIMS * 4 + 8 * NEXP * 8)    // 8 x rows + lgd[8][64] doubles

__global__ __launch_bounds__(256)
void k_fix(const float* __restrict__ x,
           const float* __restrict__ W,
           const float* __restrict__ bias,
           float* __restrict__ out)
{
    extern __shared__ __align__(16) char fsm[];
    float*  xs  = (float*)fsm;                    // [8][DIMS]
    double* lgd = (double*)(fsm + 8 * DIMS * 4);  // [8][NEXP]

    const int tid  = threadIdx.x;
    const int w    = tid >> 5;
    const int lane = tid & 31;
    const int cnt  = min(g_cnt, CAP);

    for (int s0 = blockIdx.x * 8; s0 < cnt; s0 += gridDim.x * 8) {
        const int ngrp = min(8, cnt - s0);

        for (int g = 0; g < ngrp; g++) {
            const float4* xr = (const float4*)(x + (size_t)g_susp[s0 + g] * DIMS);
            for (int i = tid; i < DIMS / 4; i += 256)
                ((float4*)(xs + g * DIMS))[i] = xr[i];
        }
        __syncthreads();

        // warp w: experts w*8..w*8+7 for all 8 tokens simultaneously.
        float acc8[8][8];
#pragma unroll
        for (int g = 0; g < 8; g++)
#pragma unroll
            for (int e = 0; e < 8; e++) acc8[g][e] = 0.0f;

#pragma unroll 1
        for (int it = 0; it < 32; it++) {
            float4 wv[8];
#pragma unroll
            for (int e = 0; e < 8; e++)
                wv[e] = ((const float4*)(W + (size_t)(w * 8 + e) * DIMS))[lane + 32 * it];
#pragma unroll
            for (int g = 0; g < 8; g++) {
                float4 xv = ((const float4*)(xs + g * DIMS))[lane + 32 * it];
#pragma unroll
                for (int e = 0; e < 8; e++) {
                    acc8[g][e] = fmaf(xv.x, wv[e].x, acc8[g][e]);
                    acc8[g][e] = fmaf(xv.y, wv[e].y, acc8[g][e]);
                    acc8[g][e] = fmaf(xv.z, wv[e].z, acc8[g][e]);
                    acc8[g][e] = fmaf(xv.w, wv[e].w, acc8[g][e]);
                }
            }
        }
#pragma unroll 1
        for (int g = 0; g < 8; g++)
#pragma unroll 1
            for (int e = 0; e < 8; e++) {
                double d = (double)acc8[g][e];
#pragma unroll
                for (int off = 16; off > 0; off >>= 1)
                    d += __shfl_down_sync(0xffffffffu, d, off);
                if (lane == 0) lgd[g * NEXP + w * 8 + e] = d + (double)bias[w * 8 + e];
            }
        __syncthreads();

        if (tid < ngrp) {
            const int t = g_susp[s0 + tid];
            const double* row = lgd + tid * NEXP;
            double m1 = -1e300, m2 = -1e300;
            int i1 = 0, i2 = 0;
            for (int e = 0; e < NEXP; e++) {
                double v = row[e];
                if (v > m1)      { m2 = m1; i2 = i1; m1 = v; i1 = e; }
                else if (v > m2) { m2 = v;  i2 = e; }
            }
            double e21 = exp(m2 - m1);
            double w1v = 1.0 / (1.0 + e21);
            out[2 * t + 0] = (float)i1;
            out[2 * t + 1] = (float)i2;
            out[2 * NTOK + 2 * t + 0] = (float)w1v;
            out[2 * NTOK + 2 * t + 1] = (float)(e21 * w1v);
        }
        __syncthreads();
    }
}

extern "C" void kernel_launch(void* const* d_in, const int* in_sizes, int n_in,
                              void* d_out, int out_size)
{
    const float* x = (const float*)d_in[0];   // (4, 4096, 4096) f32
    const float* W = (const float*)d_in[1];   // (64, 4096) f32
    const float* b = (const float*)d_in[2];   // (64,) f32
    float* out = (float*)d_out;
    (void)in_sizes; (void)n_in; (void)out_size;

    cudaFuncSetAttribute(k_main, cudaFuncAttributeMaxDynamicSharedMemorySize, SM_TOT);
    cudaFuncSetAttribute(k_fix,  cudaFuncAttributeMaxDynamicSharedMemorySize, FIX_SM);

    k_prep<<<64, 256>>>(W);                       // also resets g_cnt
    k_main<<<NTOK / TN, 256, SM_TOT>>>(x, b, out);
    k_fix<<<296, 256, FIX_SM>>>(x, W, b, out);
}

// round 15
// speedup vs baseline: 2.1611x; 1.1050x over previous
#include <cuda_runtime.h>
#include <cstdint>
#include <math.h>

// MoE router: logits = x @ W^T + b, top-2, masked softmax.
// k_prep: W -> tf32(rna) once (+ resets suspect counter).
// k_main: single-pass tf32 mma.sync, ks-split warp org (warp = 2 m16 x 8 n8,
//         fixed k-slice; 4 partial acc sets summed in epilogue). One barrier/chunk.
// k_fix:  exact recompute of tokens with top-2/3 gap < 4e-3 (20 sigma).
// Output f32: [idx 32768][w 32768].

#define NTOK 16384
#define DIMS 4096
#define NEXP 64
#define TN   64              // tokens per CTA
#define KC   32
#define NCH  (DIMS / KC)     // 128
#define LDT  36              // smem tile row stride (floats)
#define NST  4               // cp.async ring slots
#define GAP_THR 4e-3f
#define CAP  16384

#define TILE_B   (64 * LDT * 4)          // 9216 B
#define STAGE_B  (2 * TILE_B)            // W tile + x tile
#define SM_BIAS  (NST * STAGE_B)         // 73728
#define SM_TOT   (SM_BIAS + 256)
#define LGR      (64 * 68)               // logits region stride (floats) per ks-group

__device__ int   g_cnt = 0;
__device__ int   g_susp[CAP];
__device__ float g_Wt[NEXP * DIMS];      // tf32(rna)-rounded W

static __device__ __forceinline__ uint32_t smem_u32(const void* p) {
    uint32_t a;
    asm("{ .reg .u64 t; cvta.to.shared.u64 t, %1; cvt.u32.u64 %0, t; }" : "=r"(a) : "l"(p));
    return a;
}
static __device__ __forceinline__ void cp16(uint32_t dst, const void* src) {
    asm volatile("cp.async.cg.shared.global [%0], [%1], 16;" :: "r"(dst), "l"(src) : "memory");
}
#define CP_COMMIT() asm volatile("cp.async.commit_group;" ::: "memory")
#define CP_WAIT2()  asm volatile("cp.async.wait_group 2;" ::: "memory")

static __device__ __forceinline__ uint32_t tf32r(float x) {
    uint32_t u;
    asm("cvt.rna.tf32.f32 %0, %1;" : "=r"(u) : "f"(x));
    return u;
}

static __device__ __forceinline__ void mma8(float c[4],
                                            uint32_t a0, uint32_t a1, uint32_t a2, uint32_t a3,
                                            uint32_t b0, uint32_t b1) {
    asm volatile(
        "mma.sync.aligned.m16n8k8.row.col.f32.tf32.tf32.f32 "
        "{%0,%1,%2,%3}, {%4,%5,%6,%7}, {%8,%9}, {%0,%1,%2,%3};"
        : "+f"(c[0]), "+f"(c[1]), "+f"(c[2]), "+f"(c[3])
        : "r"(a0), "r"(a1), "r"(a2), "r"(a3), "r"(b0), "r"(b1));
}

// ---------------- kernel 0: round W to tf32 (rna); reset counter ----------------
__global__ __launch_bounds__(256)
void k_prep(const float* __restrict__ W)
{
    if (blockIdx.x == 0 && threadIdx.x == 0) g_cnt = 0;
    int base = (blockIdx.x * 256 + threadIdx.x) * 4;
    const int total = NEXP * DIMS;
    for (int i = base; i < total; i += gridDim.x * 256 * 4) {
        float4 v = *(const float4*)(W + i);
        uint4 u;
        u.x = tf32r(v.x); u.y = tf32r(v.y); u.z = tf32r(v.z); u.w = tf32r(v.w);
        *(uint4*)(g_Wt + i) = u;
    }
}

// ---------------- kernel 1: main GEMM + epilogue ----------------
// A = W (4 m16 tiles), B = tokens (8 n8 tiles/CTA).
// Warp org: wm = wid&1 (expert half, 2 m16 tiles), wks = wid>>1 (fixed k-step).
__global__ __launch_bounds__(256, 2)
void k_main(const float* __restrict__ x,
            const float* __restrict__ bias,
            float* __restrict__ out)
{
    extern __shared__ __align__(16) char smem[];
    const uint32_t sb = smem_u32(smem);
    float* biasS = (float*)(smem + SM_BIAS);

    const int tid  = threadIdx.x;
    const int wid  = tid >> 5;
    const int lane = tid & 31;
    const int wm   = wid & 1;
    const int wks  = wid >> 1;         // 0..3, fixed k-step slice
    const int bm   = blockIdx.x * TN;

    if (tid < NEXP) biasS[tid] = bias[tid];

    const float* wsrc[2]; const float* xsrc[2]; uint32_t wdst[2], xdst[2];
#pragma unroll
    for (int j = 0; j < 2; j++) {
        int c = tid + 256 * j, row = c >> 3, q = c & 7;
        wsrc[j] = g_Wt + (size_t)row * DIMS + q * 4;
        xsrc[j] = x + (size_t)(bm + row) * DIMS + q * 4;
        wdst[j] = sb + row * (LDT * 4) + q * 16;
        xdst[j] = sb + TILE_B + row * (LDT * 4) + q * 16;
    }

    // fragment offsets (chunk-invariant; include the warp's fixed ks*8)
    int aoff[2], boff[8];
#pragma unroll
    for (int mt = 0; mt < 2; mt++)
        aoff[mt] = (wm * 32 + mt * 16 + (lane >> 2)) * LDT + (lane & 3) + wks * 8;
#pragma unroll
    for (int nt = 0; nt < 8; nt++)
        boff[nt] = (nt * 8 + (lane >> 2)) * LDT + (lane & 3) + wks * 8;

    float acc[2][8][4];
#pragma unroll
    for (int mt = 0; mt < 2; mt++)
#pragma unroll
        for (int nt = 0; nt < 8; nt++)
#pragma unroll
            for (int q = 0; q < 4; q++) acc[mt][nt][q] = 0.0f;

    // prologue: chunks 0,1 into slots 0,1
#pragma unroll
    for (int p = 0; p < 2; p++) {
        uint32_t so = p * STAGE_B;
#pragma unroll
        for (int j = 0; j < 2; j++) {
            cp16(wdst[j] + so, wsrc[j] + p * KC);
            cp16(xdst[j] + so, xsrc[j] + p * KC);
        }
        CP_COMMIT();
    }

    for (int i = 0; i < NCH; i++) {
        // issue chunk i+2 (slot freed by chunk i-2, complete before iter i-1's barrier)
        if (i + 2 < NCH) {
            uint32_t so = ((i + 2) % NST) * STAGE_B;
            const int ko = (i + 2) * KC;
#pragma unroll
            for (int j = 0; j < 2; j++) {
                cp16(wdst[j] + so, wsrc[j] + ko);
                cp16(xdst[j] + so, xsrc[j] + ko);
            }
        }
        CP_COMMIT();
        CP_WAIT2();            // chunk i's data landed; i+1, i+2 may pend
        __syncthreads();       // single barrier per chunk

        const uint32_t* Wt = (const uint32_t*)(smem + (i % NST) * STAGE_B);
        const uint32_t* Xt = (const uint32_t*)(smem + (i % NST) * STAGE_B + TILE_B);

        uint32_t a[2][4];
#pragma unroll
        for (int mt = 0; mt < 2; mt++) {
            a[mt][0] = Wt[aoff[mt]];
            a[mt][1] = Wt[aoff[mt] + 8 * LDT];
            a[mt][2] = Wt[aoff[mt] + 4];
            a[mt][3] = Wt[aoff[mt] + 8 * LDT + 4];
        }
#pragma unroll
        for (int nt = 0; nt < 8; nt++) {
            uint32_t b0 = tf32r(__uint_as_float(Xt[boff[nt]]));
            uint32_t b1 = tf32r(__uint_as_float(Xt[boff[nt] + 4]));
            mma8(acc[0][nt], a[0][0], a[0][1], a[0][2], a[0][3], b0, b1);
            mma8(acc[1][nt], a[1][0], a[1][1], a[1][2], a[1][3], b0, b1);
        }
    }
    __syncthreads();           // all computes done before smem reuse

    // epilogue: each ks-group scatters partials to its own region [token][expert]
    float* lg = (float*)smem + wks * LGR;
#pragma unroll
    for (int mt = 0; mt < 2; mt++) {
        const int m = wm * 32 + mt * 16 + (lane >> 2);
#pragma unroll
        for (int nt = 0; nt < 8; nt++) {
            const int n = nt * 8 + (lane & 3) * 2;
            lg[n * 68 + m]           = acc[mt][nt][0];
            lg[(n + 1) * 68 + m]     = acc[mt][nt][1];
            lg[n * 68 + m + 8]       = acc[mt][nt][2];
            lg[(n + 1) * 68 + m + 8] = acc[mt][nt][3];
        }
    }
    __syncthreads();

    if (tid < TN) {
        const float* r0 = (float*)smem + tid * 68;
        float m1 = -INFINITY, m2 = -INFINITY, m3 = -INFINITY;
        int   i1 = 0, i2 = 0;
#pragma unroll
        for (int e = 0; e < NEXP; e++) {
            float v = (r0[e] + r0[LGR + e]) + (r0[2 * LGR + e] + r0[3 * LGR + e]) + biasS[e];
            if (v > m1)      { m3 = m2; m2 = m1; i2 = i1; m1 = v; i1 = e; }
            else if (v > m2) { m3 = m2; m2 = v;  i2 = e; }
            else if (v > m3) { m3 = v; }
        }
        const int gt = bm + tid;
        if ((m1 - m2 < GAP_THR) || (m2 - m3 < GAP_THR)) {
            int slot = atomicAdd(&g_cnt, 1);
            if (slot < CAP) g_susp[slot] = gt;
        }
        float e21 = expf(m2 - m1);
        float w1v = 1.0f / (1.0f + e21);
        out[2 * gt + 0] = (float)i1;
        out[2 * gt + 1] = (float)i2;
        out[2 * NTOK + 2 * gt + 0] = w1v;
        out[2 * NTOK + 2 * gt + 1] = e21 * w1v;
    }
}

// ---------------- kernel 2: exact fixup, 8 suspects per block ----------------
#define FIX_SM (8 * DIMS * 4 + 8 * NEXP * 8)    // 8 x rows + lgd[8][64] doubles

__global__ __launch_bounds__(256)
void k_fix(const float* __restrict__ x,
           const float* __restrict__ W,
           const float* __restrict__ bias,
           float* __restrict__ out)
{
    extern __shared__ __align__(16) char fsm[];
    float*  xs  = (float*)fsm;                    // [8][DIMS]
    double* lgd = (double*)(fsm + 8 * DIMS * 4);  // [8][NEXP]

    const int tid  = threadIdx.x;
    const int w    = tid >> 5;
    const int lane = tid & 31;
    const int cnt  = min(g_cnt, CAP);

    for (int s0 = blockIdx.x * 8; s0 < cnt; s0 += gridDim.x * 8) {
        const int ngrp = min(8, cnt - s0);

        for (int g = 0; g < ngrp; g++) {
            const float4* xr = (const float4*)(x + (size_t)g_susp[s0 + g] * DIMS);
            for (int i = tid; i < DIMS / 4; i += 256)
                ((float4*)(xs + g * DIMS))[i] = xr[i];
        }
        __syncthreads();

        // warp w: experts w*8..w*8+7 for all 8 tokens simultaneously
        float acc8[8][8];
#pragma unroll
        for (int g = 0; g < 8; g++)
#pragma unroll
            for (int e = 0; e < 8; e++) acc8[g][e] = 0.0f;

#pragma unroll 1
        for (int it = 0; it < 32; it++) {
            float4 wv[8];
#pragma unroll
            for (int e = 0; e < 8; e++)
                wv[e] = ((const float4*)(W + (size_t)(w * 8 + e) * DIMS))[lane + 32 * it];
#pragma unroll
            for (int g = 0; g < 8; g++) {
                float4 xv = ((const float4*)(xs + g * DIMS))[lane + 32 * it];
#pragma unroll
                for (int e = 0; e < 8; e++) {
                    acc8[g][e] = fmaf(xv.x, wv[e].x, acc8[g][e]);
                    acc8[g][e] = fmaf(xv.y, wv[e].y, acc8[g][e]);
                    acc8[g][e] = fmaf(xv.z, wv[e].z, acc8[g][e]);
                    acc8[g][e] = fmaf(xv.w, wv[e].w, acc8[g][e]);
                }
            }
        }
#pragma unroll 1
        for (int g = 0; g < 8; g++)
#pragma unroll 1
            for (int e = 0; e < 8; e++) {
                double d = (double)acc8[g][e];
#pragma unroll
                for (int off = 16; off > 0; off >>= 1)
                    d += __shfl_down_sync(0xffffffffu, d, off);
                if (lane == 0) lgd[g * NEXP + w * 8 + e] = d + (double)bias[w * 8 + e];
            }
        __syncthreads();

        if (tid < ngrp) {
            const int t = g_susp[s0 + tid];
            const double* row = lgd + tid * NEXP;
            double m1 = -1e300, m2 = -1e300;
            int i1 = 0, i2 = 0;
            for (int e = 0; e < NEXP; e++) {
                double v = row[e];
                if (v > m1)      { m2 = m1; i2 = i1; m1 = v; i1 = e; }
                else if (v > m2) { m2 = v;  i2 = e; }
            }
            double e21 = exp(m2 - m1);
            double w1v = 1.0 / (1.0 + e21);
            out[2 * t + 0] = (float)i1;
            out[2 * t + 1] = (float)i2;
            out[2 * NTOK + 2 * t + 0] = (float)w1v;
            out[2 * NTOK + 2 * t + 1] = (float)(e21 * w1v);
        }
        __syncthreads();
    }
}

extern "C" void kernel_launch(void* const* d_in, const int* in_sizes, int n_in,
                              void* d_out, int out_size)
{
    const float* x = (const float*)d_in[0];   // (4, 4096, 4096) f32
    const float* W = (const float*)d_in[1];   // (64, 4096) f32
    const float* b = (const float*)d_in[2];   // (64,) f32
    float* out = (float*)d_out;
    (void)in_sizes; (void)n_in; (void)out_size;

    cudaFuncSetAttribute(k_main, cudaFuncAttributeMaxDynamicSharedMemorySize, SM_TOT);
    cudaFuncSetAttribute(k_fix,  cudaFuncAttributeMaxDynamicSharedMemorySize, FIX_SM);

    k_prep<<<64, 256>>>(W);                       // also resets g_cnt
    k_main<<<NTOK / TN, 256, SM_TOT>>>(x, b, out);
    k_fix<<<148, 256, FIX_SM>>>(x, W, b, out);
}

// round 16
// speedup vs baseline: 2.2459x; 1.0393x over previous
#include <cuda_runtime.h>
#include <cstdint>
#include <math.h>

// MoE router: logits = x @ W^T + b, top-2, masked softmax.
// k_main: single-pass tf32 mma.sync with RAW fp32 bits as tf32 operands
//         (HW uses high 19 bits => RZ truncation; x-trunc shared across experts,
//         gap error sigma ~3e-4). KC=64 chunks, NST=3 cp.async ring, ks-split
//         warps, one barrier/chunk. Tokens with top-2/3 gap < 4e-3 flagged.
// k_fix:  exact recompute (fp32 chains + double reduce) of flagged tokens;
//         last block resets counters.
// Output f32: [idx 32768][w 32768].

#define NTOK 16384
#define DIMS 4096
#define NEXP 64
#define TN   64              // tokens per CTA
#define KC   64
#define NCH  (DIMS / KC)     // 64
#define LDT  68              // smem row stride (floats): 64 data + 4 pad, conflict-free
#define NST  3               // cp.async ring slots
#define GAP_THR 4e-3f
#define CAP  16384

#define TILE_B   (64 * LDT * 4)          // 17408 B (64 x 64 f32 tile, padded)
#define STAGE_B  (2 * TILE_B)            // W tile + x tile = 34816
#define SM_BIAS  (NST * STAGE_B)         // 104448
#define SM_TOT   (SM_BIAS + 256)         // 104704; x2 CTA/SM = 209408 <= 227KB
#define LGR      (64 * 68)               // logits partial region stride (floats)

__device__ int g_cnt  = 0;
__device__ int g_done = 0;
__device__ int g_susp[CAP];

static __device__ __forceinline__ uint32_t smem_u32(const void* p) {
    uint32_t a;
    asm("{ .reg .u64 t; cvta.to.shared.u64 t, %1; cvt.u32.u64 %0, t; }" : "=r"(a) : "l"(p));
    return a;
}
static __device__ __forceinline__ void cp16(uint32_t dst, const void* src) {
    asm volatile("cp.async.cg.shared.global [%0], [%1], 16;" :: "r"(dst), "l"(src) : "memory");
}
#define CP_COMMIT() asm volatile("cp.async.commit_group;" ::: "memory")
#define CP_WAIT1()  asm volatile("cp.async.wait_group 1;" ::: "memory")

static __device__ __forceinline__ void mma8(float c[4],
                                            uint32_t a0, uint32_t a1, uint32_t a2, uint32_t a3,
                                            uint32_t b0, uint32_t b1) {
    asm volatile(
        "mma.sync.aligned.m16n8k8.row.col.f32.tf32.tf32.f32 "
        "{%0,%1,%2,%3}, {%4,%5,%6,%7}, {%8,%9}, {%0,%1,%2,%3};"
        : "+f"(c[0]), "+f"(c[1]), "+f"(c[2]), "+f"(c[3])
        : "r"(a0), "r"(a1), "r"(a2), "r"(a3), "r"(b0), "r"(b1));
}

// ---------------- kernel 1: main GEMM + epilogue ----------------
// A = W (4 m16 tiles, read DIRECT from W as raw tf32 bits), B = tokens (8 n8).
// Warp org: wm = wid&1 (expert half, 2 m16), wks = wid>>1 (2 fixed k-steps).
__global__ __launch_bounds__(256, 2)
void k_main(const float* __restrict__ x,
            const float* __restrict__ W,
            const float* __restrict__ bias,
            float* __restrict__ out)
{
    extern __shared__ __align__(16) char smem[];
    const uint32_t sb = smem_u32(smem);
    float* biasS = (float*)(smem + SM_BIAS);

    const int tid  = threadIdx.x;
    const int wid  = tid >> 5;
    const int lane = tid & 31;
    const int wm   = wid & 1;
    const int wks  = wid >> 1;         // 0..3 -> k offsets wks*16 + {0,8}
    const int bm   = blockIdx.x * TN;

    if (tid < NEXP) biasS[tid] = bias[tid];

    // cp.async staging: each tile = 64 rows x 64 f32 = 1024 x 16B chunks; 4/thread/tile.
    const float* wsrc[4]; const float* xsrc[4]; uint32_t wdst[4], xdst[4];
#pragma unroll
    for (int j = 0; j < 4; j++) {
        int c = tid + 256 * j, row = c >> 4, q = c & 15;
        wsrc[j] = W + (size_t)row * DIMS + q * 4;
        xsrc[j] = x + (size_t)(bm + row) * DIMS + q * 4;
        wdst[j] = sb + row * (LDT * 4) + q * 16;
        xdst[j] = sb + TILE_B + row * (LDT * 4) + q * 16;
    }

    // fragment offsets (chunk-invariant; include warp's fixed wks*16)
    int aoff[2], boff[8];
#pragma unroll
    for (int mt = 0; mt < 2; mt++)
        aoff[mt] = (wm * 32 + mt * 16 + (lane >> 2)) * LDT + (lane & 3) + wks * 16;
#pragma unroll
    for (int nt = 0; nt < 8; nt++)
        boff[nt] = (nt * 8 + (lane >> 2)) * LDT + (lane & 3) + wks * 16;

    float acc[2][8][4];
#pragma unroll
    for (int mt = 0; mt < 2; mt++)
#pragma unroll
        for (int nt = 0; nt < 8; nt++)
#pragma unroll
            for (int q = 0; q < 4; q++) acc[mt][nt][q] = 0.0f;

    // prologue: chunks 0,1 into slots 0,1
#pragma unroll
    for (int p = 0; p < 2; p++) {
        uint32_t so = p * STAGE_B;
#pragma unroll
        for (int j = 0; j < 4; j++) {
            cp16(wdst[j] + so, wsrc[j] + p * KC);
            cp16(xdst[j] + so, xsrc[j] + p * KC);
        }
        CP_COMMIT();
    }

    for (int i = 0; i < NCH; i++) {
        CP_WAIT1();            // chunk i complete (i+1 may pend)
        __syncthreads();       // single barrier: publishes smem + closes chunk i-1 reads

        // issue chunk i+2 into slot (i+2)%3 == (i-1)%3 — safe AFTER the barrier
        if (i + 2 < NCH) {
            uint32_t so = ((i + 2) % NST) * STAGE_B;
            const int ko = (i + 2) * KC;
#pragma unroll
            for (int j = 0; j < 4; j++) {
                cp16(wdst[j] + so, wsrc[j] + ko);
                cp16(xdst[j] + so, xsrc[j] + ko);
            }
        }
        CP_COMMIT();

        const uint32_t* Wt = (const uint32_t*)(smem + (i % NST) * STAGE_B);
        const uint32_t* Xt = (const uint32_t*)(smem + (i % NST) * STAGE_B + TILE_B);

#pragma unroll
        for (int ks2 = 0; ks2 < 2; ks2++) {
            const int k8 = ks2 * 8;
            uint32_t a[2][4];
#pragma unroll
            for (int mt = 0; mt < 2; mt++) {
                a[mt][0] = Wt[aoff[mt] + k8];
                a[mt][1] = Wt[aoff[mt] + 8 * LDT + k8];
                a[mt][2] = Wt[aoff[mt] + k8 + 4];
                a[mt][3] = Wt[aoff[mt] + 8 * LDT + k8 + 4];
            }
#pragma unroll
            for (int nt = 0; nt < 8; nt++) {
                uint32_t b0 = Xt[boff[nt] + k8];        // raw fp32 bits as tf32
                uint32_t b1 = Xt[boff[nt] + k8 + 4];
                mma8(acc[0][nt], a[0][0], a[0][1], a[0][2], a[0][3], b0, b1);
                mma8(acc[1][nt], a[1][0], a[1][1], a[1][2], a[1][3], b0, b1);
            }
        }
    }
    __syncthreads();           // all computes done before smem reuse

    // epilogue: each ks-group scatters partials to its own region [token][expert]
    float* lg = (float*)smem + wks * LGR;
#pragma unroll
    for (int mt = 0; mt < 2; mt++) {
        const int m = wm * 32 + mt * 16 + (lane >> 2);
#pragma unroll
        for (int nt = 0; nt < 8; nt++) {
            const int n = nt * 8 + (lane & 3) * 2;
            lg[n * 68 + m]           = acc[mt][nt][0];
            lg[(n + 1) * 68 + m]     = acc[mt][nt][1];
            lg[n * 68 + m + 8]       = acc[mt][nt][2];
            lg[(n + 1) * 68 + m + 8] = acc[mt][nt][3];
        }
    }
    __syncthreads();

    if (tid < TN) {
        const float* r0 = (float*)smem + tid * 68;
        float m1 = -INFINITY, m2 = -INFINITY, m3 = -INFINITY;
        int   i1 = 0, i2 = 0;
#pragma unroll
        for (int e = 0; e < NEXP; e++) {
            float v = (r0[e] + r0[LGR + e]) + (r0[2 * LGR + e] + r0[3 * LGR + e]) + biasS[e];
            if (v > m1)      { m3 = m2; m2 = m1; i2 = i1; m1 = v; i1 = e; }
            else if (v > m2) { m3 = m2; m2 = v;  i2 = e; }
            else if (v > m3) { m3 = v; }
        }
        const int gt = bm + tid;
        if ((m1 - m2 < GAP_THR) || (m2 - m3 < GAP_THR)) {
            int slot = atomicAdd(&g_cnt, 1);
            if (slot < CAP) g_susp[slot] = gt;
        }
        float e21 = expf(m2 - m1);
        float w1v = 1.0f / (1.0f + e21);
        out[2 * gt + 0] = (float)i1;
        out[2 * gt + 1] = (float)i2;
        out[2 * NTOK + 2 * gt + 0] = w1v;
        out[2 * NTOK + 2 * gt + 1] = e21 * w1v;
    }
}

// ---------------- kernel 2: exact fixup, 8 suspects per block; resets counters ----------------
#define FIX_SM (8 * DIMS * 4 + 8 * NEXP * 8)    // 8 x rows + lgd[8][64] doubles

__global__ __launch_bounds__(256)
void k_fix(const float* __restrict__ x,
           const float* __restrict__ W,
           const float* __restrict__ bias,
           float* __restrict__ out)
{
    extern __shared__ __align__(16) char fsm[];
    float*  xs  = (float*)fsm;                    // [8][DIMS]
    double* lgd = (double*)(fsm + 8 * DIMS * 4);  // [8][NEXP]

    const int tid  = threadIdx.x;
    const int w    = tid >> 5;
    const int lane = tid & 31;
    const int cnt  = min(g_cnt, CAP);

    for (int s0 = blockIdx.x * 8; s0 < cnt; s0 += gridDim.x * 8) {
        const int ngrp = min(8, cnt - s0);

        for (int g = 0; g < ngrp; g++) {
            const float4* xr = (const float4*)(x + (size_t)g_susp[s0 + g] * DIMS);
            for (int i = tid; i < DIMS / 4; i += 256)
                ((float4*)(xs + g * DIMS))[i] = xr[i];
        }
        __syncthreads();

        float acc8[8][8];
#pragma unroll
        for (int g = 0; g < 8; g++)
#pragma unroll
            for (int e = 0; e < 8; e++) acc8[g][e] = 0.0f;

#pragma unroll 1
        for (int it = 0; it < 32; it++) {
            float4 wv[8];
#pragma unroll
            for (int e = 0; e < 8; e++)
                wv[e] = ((const float4*)(W + (size_t)(w * 8 + e) * DIMS))[lane + 32 * it];
#pragma unroll
            for (int g = 0; g < 8; g++) {
                float4 xv = ((const float4*)(xs + g * DIMS))[lane + 32 * it];
#pragma unroll
                for (int e = 0; e < 8; e++) {
                    acc8[g][e] = fmaf(xv.x, wv[e].x, acc8[g][e]);
                    acc8[g][e] = fmaf(xv.y, wv[e].y, acc8[g][e]);
                    acc8[g][e] = fmaf(xv.z, wv[e].z, acc8[g][e]);
                    acc8[g][e] = fmaf(xv.w, wv[e].w, acc8[g][e]);
                }
            }
        }
#pragma unroll 1
        for (int g = 0; g < 8; g++)
#pragma unroll 1
            for (int e = 0; e < 8; e++) {
                double d = (double)acc8[g][e];
#pragma unroll
                for (int off = 16; off > 0; off >>= 1)
                    d += __shfl_down_sync(0xffffffffu, d, off);
                if (lane == 0) lgd[g * NEXP + w * 8 + e] = d + (double)bias[w * 8 + e];
            }
        __syncthreads();

        if (tid < ngrp) {
            const int t = g_susp[s0 + tid];
            const double* row = lgd + tid * NEXP;
            double m1 = -1e300, m2 = -1e300;
            int i1 = 0, i2 = 0;
            for (int e = 0; e < NEXP; e++) {
                double v = row[e];
                if (v > m1)      { m2 = m1; i2 = i1; m1 = v; i1 = e; }
                else if (v > m2) { m2 = v;  i2 = e; }
            }
            double e21 = exp(m2 - m1);
            double w1v = 1.0 / (1.0 + e21);
            out[2 * t + 0] = (float)i1;
            out[2 * t + 1] = (float)i2;
            out[2 * NTOK + 2 * t + 0] = (float)w1v;
            out[2 * NTOK + 2 * t + 1] = (float)(e21 * w1v);
        }
        __syncthreads();
    }

    // last finished block resets the counters for the next graph replay
    __syncthreads();
    if (tid == 0) {
        int d = atomicAdd(&g_done, 1);
        if (d == (int)gridDim.x - 1) { g_cnt = 0; g_done = 0; }
    }
}

extern "C" void kernel_launch(void* const* d_in, const int* in_sizes, int n_in,
                              void* d_out, int out_size)
{
    const float* x = (const float*)d_in[0];   // (4, 4096, 4096) f32
    const float* W = (const float*)d_in[1];   // (64, 4096) f32
    const float* b = (const float*)d_in[2];   // (64,) f32
    float* out = (float*)d_out;
    (void)in_sizes; (void)n_in; (void)out_size;

    cudaFuncSetAttribute(k_main, cudaFuncAttributeMaxDynamicSharedMemorySize, SM_TOT);
    cudaFuncSetAttribute(k_fix,  cudaFuncAttributeMaxDynamicSharedMemorySize, FIX_SM);

    k_main<<<NTOK / TN, 256, SM_TOT>>>(x, W, b, out);
    k_fix<<<148, 256, FIX_SM>>>(x, W, b, out);
}

// round 17
// speedup vs baseline: 2.6315x; 1.1717x over previous
#include <cuda_runtime.h>
#include <cstdint>
#include <math.h>

// MoE router: logits = x @ W^T + b, top-2, masked softmax.
// k_prep: W -> tf32(rna) into g_Wt; resets suspect counter.
// k_main: single-pass tf32 mma.sync (A = rna W, B = x cvt-rna at frag load),
//         KC=64, NST=3 cp.async ring, ks-split warps, one barrier/chunk.
//         sigma_gap ~1.5e-4; tokens with top-2/3 gap < 1.5e-3 (10 sigma) flagged.
// k_fix:  exact recompute, 2 suspects/block, pipelined W loads, high occupancy.
// Output f32: [idx 32768][w 32768].

#define NTOK 16384
#define DIMS 4096
#define NEXP 64
#define TN   64              // tokens per CTA
#define KC   64
#define NCH  (DIMS / KC)     // 64
#define LDT  68              // smem row stride (floats)
#define NST  3               // cp.async ring slots
#define GAP_THR 1.5e-3f
#define CAP  16384

#define TILE_B   (64 * LDT * 4)          // 17408 B
#define STAGE_B  (2 * TILE_B)            // 34816
#define SM_BIAS  (NST * STAGE_B)         // 104448
#define SM_TOT   (SM_BIAS + 256)         // 104704; x2 CTA/SM fits 227KB
#define LGR      (64 * 68)

__device__ int   g_cnt = 0;
__device__ int   g_susp[CAP];
__device__ float g_Wt[NEXP * DIMS];      // tf32(rna)-rounded W

static __device__ __forceinline__ uint32_t smem_u32(const void* p) {
    uint32_t a;
    asm("{ .reg .u64 t; cvta.to.shared.u64 t, %1; cvt.u32.u64 %0, t; }" : "=r"(a) : "l"(p));
    return a;
}
static __device__ __forceinline__ void cp16(uint32_t dst, const void* src) {
    asm volatile("cp.async.cg.shared.global [%0], [%1], 16;" :: "r"(dst), "l"(src) : "memory");
}
#define CP_COMMIT() asm volatile("cp.async.commit_group;" ::: "memory")
#define CP_WAIT1()  asm volatile("cp.async.wait_group 1;" ::: "memory")

static __device__ __forceinline__ uint32_t tf32r(float x) {
    uint32_t u;
    asm("cvt.rna.tf32.f32 %0, %1;" : "=r"(u) : "f"(x));
    return u;
}

static __device__ __forceinline__ void mma8(float c[4],
                                            uint32_t a0, uint32_t a1, uint32_t a2, uint32_t a3,
                                            uint32_t b0, uint32_t b1) {
    asm volatile(
        "mma.sync.aligned.m16n8k8.row.col.f32.tf32.tf32.f32 "
        "{%0,%1,%2,%3}, {%4,%5,%6,%7}, {%8,%9}, {%0,%1,%2,%3};"
        : "+f"(c[0]), "+f"(c[1]), "+f"(c[2]), "+f"(c[3])
        : "r"(a0), "r"(a1), "r"(a2), "r"(a3), "r"(b0), "r"(b1));
}

// ---------------- kernel 0: W -> tf32(rna); reset counter ----------------
__global__ __launch_bounds__(256)
void k_prep(const float* __restrict__ W)
{
    if (blockIdx.x == 0 && threadIdx.x == 0) g_cnt = 0;
    int base = (blockIdx.x * 256 + threadIdx.x) * 4;
    const int total = NEXP * DIMS;
    for (int i = base; i < total; i += gridDim.x * 256 * 4) {
        float4 v = *(const float4*)(W + i);
        uint4 u;
        u.x = tf32r(v.x); u.y = tf32r(v.y); u.z = tf32r(v.z); u.w = tf32r(v.w);
        *(uint4*)(g_Wt + i) = u;
    }
}

// ---------------- kernel 1: main GEMM + epilogue ----------------
__global__ __launch_bounds__(256, 2)
void k_main(const float* __restrict__ x,
            const float* __restrict__ bias,
            float* __restrict__ out)
{
    extern __shared__ __align__(16) char smem[];
    const uint32_t sb = smem_u32(smem);
    float* biasS = (float*)(smem + SM_BIAS);

    const int tid  = threadIdx.x;
    const int wid  = tid >> 5;
    const int lane = tid & 31;
    const int wm   = wid & 1;
    const int wks  = wid >> 1;         // 0..3 -> k offsets wks*16 + {0,8}
    const int bm   = blockIdx.x * TN;

    if (tid < NEXP) biasS[tid] = bias[tid];

    const float* wsrc[4]; const float* xsrc[4]; uint32_t wdst[4], xdst[4];
#pragma unroll
    for (int j = 0; j < 4; j++) {
        int c = tid + 256 * j, row = c >> 4, q = c & 15;
        wsrc[j] = g_Wt + (size_t)row * DIMS + q * 4;
        xsrc[j] = x + (size_t)(bm + row) * DIMS + q * 4;
        wdst[j] = sb + row * (LDT * 4) + q * 16;
        xdst[j] = sb + TILE_B + row * (LDT * 4) + q * 16;
    }

    int aoff[2], boff[8];
#pragma unroll
    for (int mt = 0; mt < 2; mt++)
        aoff[mt] = (wm * 32 + mt * 16 + (lane >> 2)) * LDT + (lane & 3) + wks * 16;
#pragma unroll
    for (int nt = 0; nt < 8; nt++)
        boff[nt] = (nt * 8 + (lane >> 2)) * LDT + (lane & 3) + wks * 16;

    float acc[2][8][4];
#pragma unroll
    for (int mt = 0; mt < 2; mt++)
#pragma unroll
        for (int nt = 0; nt < 8; nt++)
#pragma unroll
            for (int q = 0; q < 4; q++) acc[mt][nt][q] = 0.0f;

    // prologue: chunks 0,1 into slots 0,1
#pragma unroll
    for (int p = 0; p < 2; p++) {
        uint32_t so = p * STAGE_B;
#pragma unroll
        for (int j = 0; j < 4; j++) {
            cp16(wdst[j] + so, wsrc[j] + p * KC);
            cp16(xdst[j] + so, xsrc[j] + p * KC);
        }
        CP_COMMIT();
    }

    for (int i = 0; i < NCH; i++) {
        CP_WAIT1();            // chunk i landed (i+1 may pend)
        __syncthreads();       // publish smem + close chunk i-1 reads

        if (i + 2 < NCH) {     // refill slot (i+2)%3 == (i-1)%3 — safe after barrier
            uint32_t so = ((i + 2) % NST) * STAGE_B;
            const int ko = (i + 2) * KC;
#pragma unroll
            for (int j = 0; j < 4; j++) {
                cp16(wdst[j] + so, wsrc[j] + ko);
                cp16(xdst[j] + so, xsrc[j] + ko);
            }
        }
        CP_COMMIT();

        const uint32_t* Wt = (const uint32_t*)(smem + (i % NST) * STAGE_B);
        const uint32_t* Xt = (const uint32_t*)(smem + (i % NST) * STAGE_B + TILE_B);

#pragma unroll
        for (int ks2 = 0; ks2 < 2; ks2++) {
            const int k8 = ks2 * 8;
            uint32_t a[2][4];
#pragma unroll
            for (int mt = 0; mt < 2; mt++) {
                a[mt][0] = Wt[aoff[mt] + k8];
                a[mt][1] = Wt[aoff[mt] + 8 * LDT + k8];
                a[mt][2] = Wt[aoff[mt] + k8 + 4];
                a[mt][3] = Wt[aoff[mt] + 8 * LDT + k8 + 4];
            }
#pragma unroll
            for (int nt = 0; nt < 8; nt++) {
                uint32_t b0 = tf32r(__uint_as_float(Xt[boff[nt] + k8]));
                uint32_t b1 = tf32r(__uint_as_float(Xt[boff[nt] + k8 + 4]));
                mma8(acc[0][nt], a[0][0], a[0][1], a[0][2], a[0][3], b0, b1);
                mma8(acc[1][nt], a[1][0], a[1][1], a[1][2], a[1][3], b0, b1);
            }
        }
    }
    __syncthreads();

    // epilogue: partials -> 4 regions [token][expert]
    float* lg = (float*)smem + wks * LGR;
#pragma unroll
    for (int mt = 0; mt < 2; mt++) {
        const int m = wm * 32 + mt * 16 + (lane >> 2);
#pragma unroll
        for (int nt = 0; nt < 8; nt++) {
            const int n = nt * 8 + (lane & 3) * 2;
            lg[n * 68 + m]           = acc[mt][nt][0];
            lg[(n + 1) * 68 + m]     = acc[mt][nt][1];
            lg[n * 68 + m + 8]       = acc[mt][nt][2];
            lg[(n + 1) * 68 + m + 8] = acc[mt][nt][3];
        }
    }
    __syncthreads();

    if (tid < TN) {
        const float* r0 = (float*)smem + tid * 68;
        float m1 = -INFINITY, m2 = -INFINITY, m3 = -INFINITY;
        int   i1 = 0, i2 = 0;
#pragma unroll
        for (int e = 0; e < NEXP; e++) {
            float v = (r0[e] + r0[LGR + e]) + (r0[2 * LGR + e] + r0[3 * LGR + e]) + biasS[e];
            if (v > m1)      { m3 = m2; m2 = m1; i2 = i1; m1 = v; i1 = e; }
            else if (v > m2) { m3 = m2; m2 = v;  i2 = e; }
            else if (v > m3) { m3 = v; }
        }
        const int gt = bm + tid;
        if ((m1 - m2 < GAP_THR) || (m2 - m3 < GAP_THR)) {
            int slot = atomicAdd(&g_cnt, 1);
            if (slot < CAP) g_susp[slot] = gt;
        }
        float e21 = expf(m2 - m1);
        float w1v = 1.0f / (1.0f + e21);
        out[2 * gt + 0] = (float)i1;
        out[2 * gt + 1] = (float)i2;
        out[2 * NTOK + 2 * gt + 0] = w1v;
        out[2 * NTOK + 2 * gt + 1] = e21 * w1v;
    }
}

// ---------------- kernel 2: exact fixup, 2 suspects/block, pipelined ----------------
#define FIX_SM (2 * DIMS * 4 + 2 * NEXP * 8)    // 2 x rows + lgd[2][64] = 33792 B

__global__ __launch_bounds__(256)
void k_fix(const float* __restrict__ x,
           const float* __restrict__ W,
           const float* __restrict__ bias,
           float* __restrict__ out)
{
    extern __shared__ __align__(16) char fsm[];
    float*  xs  = (float*)fsm;                    // [2][DIMS]
    double* lgd = (double*)(fsm + 2 * DIMS * 4);  // [2][NEXP]

    const int tid  = threadIdx.x;
    const int w    = tid >> 5;
    const int lane = tid & 31;
    const int cnt  = min(g_cnt, CAP);

    for (int s0 = blockIdx.x * 2; s0 < cnt; s0 += gridDim.x * 2) {
        const int ngrp = min(2, cnt - s0);

        for (int g = 0; g < ngrp; g++) {
            const float4* xr = (const float4*)(x + (size_t)g_susp[s0 + g] * DIMS);
            for (int i = tid; i < DIMS / 4; i += 256)
                ((float4*)(xs + g * DIMS))[i] = xr[i];
        }
        __syncthreads();

        // warp w: experts w*8..w*8+7 for both tokens; software-pipelined W loads
        float acc8[2][8];
#pragma unroll
        for (int g = 0; g < 2; g++)
#pragma unroll
            for (int e = 0; e < 8; e++) acc8[g][e] = 0.0f;

        float4 wv[8], wvn[8];
#pragma unroll
        for (int e = 0; e < 8; e++)
            wv[e] = ((const float4*)(W + (size_t)(w * 8 + e) * DIMS))[lane];

#pragma unroll 1
        for (int it = 0; it < 32; it++) {
            if (it + 1 < 32) {
#pragma unroll
                for (int e = 0; e < 8; e++)
                    wvn[e] = ((const float4*)(W + (size_t)(w * 8 + e) * DIMS))[lane + 32 * (it + 1)];
            }
            float4 xv0 = ((const float4*)(xs))[lane + 32 * it];
            float4 xv1 = ((const float4*)(xs + DIMS))[lane + 32 * it];
#pragma unroll
            for (int e = 0; e < 8; e++) {
                acc8[0][e] = fmaf(xv0.x, wv[e].x, acc8[0][e]);
                acc8[0][e] = fmaf(xv0.y, wv[e].y, acc8[0][e]);
                acc8[0][e] = fmaf(xv0.z, wv[e].z, acc8[0][e]);
                acc8[0][e] = fmaf(xv0.w, wv[e].w, acc8[0][e]);
                acc8[1][e] = fmaf(xv1.x, wv[e].x, acc8[1][e]);
                acc8[1][e] = fmaf(xv1.y, wv[e].y, acc8[1][e]);
                acc8[1][e] = fmaf(xv1.z, wv[e].z, acc8[1][e]);
                acc8[1][e] = fmaf(xv1.w, wv[e].w, acc8[1][e]);
            }
#pragma unroll
            for (int e = 0; e < 8; e++) wv[e] = wvn[e];
        }

#pragma unroll 1
        for (int g = 0; g < 2; g++)
#pragma unroll 1
            for (int e = 0; e < 8; e++) {
                double d = (double)acc8[g][e];
#pragma unroll
                for (int off = 16; off > 0; off >>= 1)
                    d += __shfl_down_sync(0xffffffffu, d, off);
                if (lane == 0) lgd[g * NEXP + w * 8 + e] = d + (double)bias[w * 8 + e];
            }
        __syncthreads();

        if (tid < ngrp) {
            const int t = g_susp[s0 + tid];
            const double* row = lgd + tid * NEXP;
            double m1 = -1e300, m2 = -1e300;
            int i1 = 0, i2 = 0;
            for (int e = 0; e < NEXP; e++) {
                double v = row[e];
                if (v > m1)      { m2 = m1; i2 = i1; m1 = v; i1 = e; }
                else if (v > m2) { m2 = v;  i2 = e; }
            }
            double e21 = exp(m2 - m1);
            double w1v = 1.0 / (1.0 + e21);
            out[2 * t + 0] = (float)i1;
            out[2 * t + 1] = (float)i2;
            out[2 * NTOK + 2 * t + 0] = (float)w1v;
            out[2 * NTOK + 2 * t + 1] = (float)(e21 * w1v);
        }
        __syncthreads();
    }
}

extern "C" void kernel_launch(void* const* d_in, const int* in_sizes, int n_in,
                              void* d_out, int out_size)
{
    const float* x = (const float*)d_in[0];   // (4, 4096, 4096) f32
    const float* W = (const float*)d_in[1];   // (64, 4096) f32
    const float* b = (const float*)d_in[2];   // (64,) f32
    float* out = (float*)d_out;
    (void)in_sizes; (void)n_in; (void)out_size;

    cudaFuncSetAttribute(k_main, cudaFuncAttributeMaxDynamicSharedMemorySize, SM_TOT);
    cudaFuncSetAttribute(k_fix,  cudaFuncAttributeMaxDynamicSharedMemorySize, FIX_SM);

    k_prep<<<64, 256>>>(W);                        // rna W + reset counter
    k_main<<<NTOK / TN, 256, SM_TOT>>>(x, b, out);
    k_fix<<<512, 256, FIX_SM>>>(x, W, b, out);
}